// round 16
// baseline (speedup 1.0000x reference)
#include <cuda_runtime.h>
#include <cstdint>

#define QPB 32   // queries per block: 256 threads / 8 lanes per query
#define CS  12   // partial-scratch column stride (words)
#define QR  168  // per-query partial region (words); 168 % 32 == 8
#define LS  24   // per-query logit region (words)

// Per-lane weight-block stride: 8 channels x NCOL cols = 24P words, padded +4
// so stride mod 32 is an odd multiple of 4 -> 8-lane LDS.128 phases tile all banks.
template <int P> struct WStride { static constexpr int v = 24 * P + 4; };

// Stage weight staging: block sl holds channels [8sl, 8sl+8) x NCOL cols.
// Within a block: col j -> 8 floats at [j*8, j*8+8): sWb[(k>>3)*S + c*8 + (k&7)].
__device__ __forceinline__ void load_wb(float* sWb, float* sB, int S,
    const float* __restrict__ we, const float* __restrict__ be,
    const float* __restrict__ ww, const float* __restrict__ bw,
    int P, int tid, int nthreads)
{
    const int NCOL = 3 * P;
    for (int i = tid; i < 64 * NCOL; i += nthreads) {
        const int c = i >> 6, k = i & 63;
        float v = (c < 2 * P) ? we[k * (2 * P) + c] : ww[k * P + (c - 2 * P)];
        sWb[(k >> 3) * S + c * 8 + (k & 7)] = v;
    }
    if (tid < NCOL) sB[tid] = (tid < 2 * P) ? be[tid] : bw[tid - 2 * P];
}

__device__ __forceinline__ void fma4(float4& acc, const float4 v, const float c) {
    acc.x = fmaf(v.x, c, acc.x); acc.y = fmaf(v.y, c, acc.y);
    acc.z = fmaf(v.z, c, acc.z); acc.w = fmaf(v.w, c, acc.w);
}

// One stage for one query on an 8-lane group; lane owns 8 channels (c4a, c4b).
template <int P>
__device__ __forceinline__ void run_stage(
    float4& c4a, float4& c4b, int sl, int g,
    const float* __restrict__ sWb,
    const float* __restrict__ sB,
    float* __restrict__ sPart,
    float* __restrict__ sLog,
    float& spx, float& spy,
    float base_x, float base_y, float sc_x, float sc_y,
    int h, int w,
    const float* __restrict__ vbase, bool active)
{
    constexpr int NCOL = 3 * P;
    constexpr int S = WStride<P>::v;

    // ---- register GEMM partials (8-channel dot per lane) -> scratch ----
    const float4* blk = reinterpret_cast<const float4*>(sWb + sl * S);
    float* myPart = sPart + g * QR;
    #pragma unroll
    for (int j = 0; j < NCOL; j++) {
        const float4 wa = blk[2 * j];
        const float4 wb = blk[2 * j + 1];
        const float pa = fmaf(c4a.x, wa.x, fmaf(c4a.y, wa.y, fmaf(c4a.z, wa.z, c4a.w * wa.w)));
        const float pb = fmaf(c4b.x, wb.x, fmaf(c4b.y, wb.y, fmaf(c4b.z, wb.z, c4b.w * wb.w)));
        myPart[j * CS + sl] = pa + pb;
    }
    __syncwarp();

    // ---- column owners sum 8 partials (2x LDS.128), add bias, publish ----
    {
        const int n0 = (NCOL < 8) ? NCOL : 8;
        if (sl < n0) {
            const float4* col = reinterpret_cast<const float4*>(myPart + sl * CS);
            const float4 a = col[0], b = col[1];
            const float s = ((a.x + a.y) + (a.z + a.w)) + ((b.x + b.y) + (b.z + b.w));
            sLog[g * LS + sl] = s + sB[sl];
        }
        if (NCOL > 8 && sl < NCOL - 8) {
            const int cidx = sl + 8;
            const float4* col = reinterpret_cast<const float4*>(myPart + cidx * CS);
            const float4 a = col[0], b = col[1];
            const float s = ((a.x + a.y) + (a.z + a.w)) + ((b.x + b.y) + (b.z + b.w));
            sLog[g * LS + cidx] = s + sB[cidx];
        }
    }
    __syncwarp();

    // ---- broadcast logits to the 8 lanes ----
    float lg[NCOL];
    {
        const float4* lq = reinterpret_cast<const float4*>(sLog + g * LS);
        #pragma unroll
        for (int v4 = 0; v4 < (NCOL + 3) / 4; v4++) {
            const float4 t = lq[v4];
            if (4 * v4 + 0 < NCOL) lg[4 * v4 + 0] = t.x;
            if (4 * v4 + 1 < NCOL) lg[4 * v4 + 1] = t.y;
            if (4 * v4 + 2 < NCOL) lg[4 * v4 + 2] = t.z;
            if (4 * v4 + 3 < NCOL) lg[4 * v4 + 3] = t.w;
        }
    }

    // ---- softmax + argmax over P (MUFU exp) ----
    float wl[P];
    float m = -1e30f; int mid = 0;
    #pragma unroll
    for (int p = 0; p < P; p++) {
        wl[p] = lg[2 * P + p];
        if (wl[p] > m) { m = wl[p]; mid = p; }   // strict > => first max (jnp.argmax)
    }
    float sum = 0.f;
    #pragma unroll
    for (int p = 0; p < P; p++) { wl[p] = __expf(wl[p] - m); sum += wl[p]; }
    const float inv = 1.0f / sum;

    // offsets use OLD speed; speed updated with delta[argmax]
    const float bx = fmaf(spx, sc_x, base_x);
    const float by = fmaf(spy, sc_y, base_y);
    spx += lg[2 * mid];
    spy += lg[2 * mid + 1];

    float4 acca = make_float4(0.f, 0.f, 0.f, 0.f);
    float4 accb = make_float4(0.f, 0.f, 0.f, 0.f);
    #pragma unroll
    for (int p = 0; p < P; p++) {
        const float x = fmaf(lg[2 * p],     sc_x, bx);
        const float y = fmaf(lg[2 * p + 1], sc_y, by);
        const float x0f = floorf(x), y0f = floorf(y);
        const float fx = x - x0f, fy = y - y0f;
        const int x0 = (int)x0f, y0 = (int)y0f;
        const int x1 = x0 + 1,   y1 = y0 + 1;

        const float wp = active ? wl[p] * inv : 0.f;
        const float wx0 = ((unsigned)x0 < (unsigned)w) ? (1.f - fx) : 0.f;
        const float wx1 = ((unsigned)x1 < (unsigned)w) ? fx         : 0.f;
        const float wy0 = ((unsigned)y0 < (unsigned)h) ? (1.f - fy) * wp : 0.f;
        const float wy1 = ((unsigned)y1 < (unsigned)h) ? fy * wp         : 0.f;

        const int xc0 = min(max(x0, 0), w - 1);
        const int xc1 = min(max(x1, 0), w - 1);
        const int r0 = min(max(y0, 0), h - 1) * w;
        const int r1 = min(max(y1, 0), h - 1) * w;

        const float* p00 = vbase + (r0 + xc0) * 64;
        const float* p01 = vbase + (r0 + xc1) * 64;
        const float* p10 = vbase + (r1 + xc0) * 64;
        const float* p11 = vbase + (r1 + xc1) * 64;

        // 8 back-to-back vector loads (32B per lane per corner)
        const float4 v00a = *reinterpret_cast<const float4*>(p00);
        const float4 v00b = *reinterpret_cast<const float4*>(p00 + 4);
        const float4 v01a = *reinterpret_cast<const float4*>(p01);
        const float4 v01b = *reinterpret_cast<const float4*>(p01 + 4);
        const float4 v10a = *reinterpret_cast<const float4*>(p10);
        const float4 v10b = *reinterpret_cast<const float4*>(p10 + 4);
        const float4 v11a = *reinterpret_cast<const float4*>(p11);
        const float4 v11b = *reinterpret_cast<const float4*>(p11 + 4);

        const float c00 = wx0 * wy0, c01 = wx1 * wy0;
        const float c10 = wx0 * wy1, c11 = wx1 * wy1;

        fma4(acca, v00a, c00); fma4(accb, v00b, c00);
        fma4(acca, v01a, c01); fma4(accb, v01b, c01);
        fma4(acca, v10a, c10); fma4(accb, v10b, c10);
        fma4(acca, v11a, c11); fma4(accb, v11b, c11);
    }
    c4a = acca;
    c4b = accb;
}

template <int P1, int P2, int P3>
__global__ __launch_bounds__(256, 3) void speed_sampler_fused(
    const float* __restrict__ curIn,
    const float* __restrict__ indices,
    const float* __restrict__ value,
    const float* __restrict__ we1, const float* __restrict__ be1,
    const float* __restrict__ ww1, const float* __restrict__ bw1,
    const float* __restrict__ we2, const float* __restrict__ be2,
    const float* __restrict__ ww2, const float* __restrict__ bw2,
    const float* __restrict__ we3, const float* __restrict__ be3,
    const float* __restrict__ ww3, const float* __restrict__ bw3,
    const int* __restrict__ hsp_p, const int* __restrict__ wsp_p,
    float* __restrict__ out,
    int BFN, int BFHW)
{
    constexpr int S1 = WStride<P1>::v, S2 = WStride<P2>::v, S3 = WStride<P3>::v;
    __shared__ __align__(16) float sWb1[8 * S1];
    __shared__ __align__(16) float sWb2[8 * S2];
    __shared__ __align__(16) float sWb3[8 * S3];
    __shared__ float sB1[3 * P1], sB2[3 * P2], sB3[3 * P3];
    __shared__ __align__(16) float sPart[QPB * QR];
    __shared__ __align__(16) float sLog[QPB * LS];

    const int tid = threadIdx.x;
    const int sl = tid & 7;             // lane within 8-lane group
    const int g  = tid >> 3;            // query slot in block, 0..31
    const int q = blockIdx.x * QPB + g;
    const int h = *hsp_p, w = *wsp_p;
    const int HW = h * w;
    const int BF = BFHW / HW;
    const int Nq = BFN / BF;
    const bool active = q < BFN;

    const float fh = (float)h, fw = (float)w;
    const float rwh = fw / fh, rhw = fh / fw;
    const float sc_x = 0.1f * rwh, sc_y = 0.1f * rhw;

    // ---- early loads + L1 prefetch of the base 2x2 neighborhood ----
    float4 c4a = make_float4(0.f, 0.f, 0.f, 0.f);
    float4 c4b = make_float4(0.f, 0.f, 0.f, 0.f);
    float base_x = -0.5f, base_y = -0.5f;
    const float* vbase = value + 8 * sl;
    if (active) {
        const float* crow = curIn + (size_t)q * 64 + 8 * sl;
        c4a = *reinterpret_cast<const float4*>(crow);
        c4b = *reinterpret_cast<const float4*>(crow + 4);
        const float2 idx = *reinterpret_cast<const float2*>(indices + (size_t)q * 2);
        base_x = fmaf(idx.x, rwh, -0.5f);
        base_y = fmaf(idx.y, rhw, -0.5f);
        const int bf = q / Nq;
        vbase += (size_t)bf * HW * 64;

        const int px0 = (int)floorf(base_x), py0 = (int)floorf(base_y);
        const int pxc0 = min(max(px0, 0), w - 1);
        const int pxc1 = min(max(px0 + 1, 0), w - 1);
        const int pr0 = min(max(py0, 0), h - 1) * w;
        const int pr1 = min(max(py0 + 1, 0), h - 1) * w;
        asm volatile("prefetch.global.L1 [%0];" :: "l"(vbase + (pr0 + pxc0) * 64));
        asm volatile("prefetch.global.L1 [%0];" :: "l"(vbase + (pr0 + pxc1) * 64));
        asm volatile("prefetch.global.L1 [%0];" :: "l"(vbase + (pr1 + pxc0) * 64));
        asm volatile("prefetch.global.L1 [%0];" :: "l"(vbase + (pr1 + pxc1) * 64));
    }

    load_wb(sWb1, sB1, S1, we1, be1, ww1, bw1, P1, tid, blockDim.x);
    load_wb(sWb2, sB2, S2, we2, be2, ww2, bw2, P2, tid, blockDim.x);
    load_wb(sWb3, sB3, S3, we3, be3, ww3, bw3, P3, tid, blockDim.x);
    __syncthreads();

    float spx = 0.f, spy = 0.f;

    run_stage<P1>(c4a, c4b, sl, g, sWb1, sB1, sPart, sLog, spx, spy, base_x, base_y, sc_x, sc_y, h, w, vbase, active);
    run_stage<P2>(c4a, c4b, sl, g, sWb2, sB2, sPart, sLog, spx, spy, base_x, base_y, sc_x, sc_y, h, w, vbase, active);
    run_stage<P3>(c4a, c4b, sl, g, sWb3, sB3, sPart, sLog, spx, spy, base_x, base_y, sc_x, sc_y, h, w, vbase, active);

    if (active) {
        // out row = 66 floats; lane owns channels [8sl, 8sl+8). (q*66 + 8sl) even.
        float* o = out + (size_t)q * 66 + 8 * sl;
        *reinterpret_cast<float2*>(o)     = make_float2(c4a.x, c4a.y);
        *reinterpret_cast<float2*>(o + 2) = make_float2(c4a.z, c4a.w);
        *reinterpret_cast<float2*>(o + 4) = make_float2(c4b.x, c4b.y);
        *reinterpret_cast<float2*>(o + 6) = make_float2(c4b.z, c4b.w);
        if (sl == 0) {
            out[(size_t)q * 66 + 64] = spx;
            out[(size_t)q * 66 + 65] = spy;
        }
    }
}

extern "C" void kernel_launch(void* const* d_in, const int* in_sizes, int n_in,
                              void* d_out, int out_size)
{
    const float* cur  = (const float*)d_in[0];
    const float* idxs = (const float*)d_in[1];
    const float* val  = (const float*)d_in[2];
    const int*   hsp  = (const int*)d_in[3];
    const int*   wsp  = (const int*)d_in[4];

    const int P1 = in_sizes[6] / 2;
    const int P2 = in_sizes[10] / 2;
    const int P3 = in_sizes[14] / 2;
    const int C  = in_sizes[5] / in_sizes[6];
    const int BFN  = in_sizes[0] / C;
    const int BFHW = in_sizes[2] / C;

    float* out = (float*)d_out;
    dim3 block(256);
    dim3 grid((BFN + QPB - 1) / QPB);

    if (P1 == 4 && P2 == 2 && P3 == 1) {
        speed_sampler_fused<4, 2, 1><<<grid, block>>>(
            cur, idxs, val,
            (const float*)d_in[5],  (const float*)d_in[6],
            (const float*)d_in[7],  (const float*)d_in[8],
            (const float*)d_in[9],  (const float*)d_in[10],
            (const float*)d_in[11], (const float*)d_in[12],
            (const float*)d_in[13], (const float*)d_in[14],
            (const float*)d_in[15], (const float*)d_in[16],
            hsp, wsp, out, BFN, BFHW);
    }
}

// round 17
// speedup vs baseline: 1.1967x; 1.1967x over previous
#include <cuda_runtime.h>
#include <cstdint>

#define QPB 16   // queries per block: 8 warps x 2 half-warp queries

// Per-lane weight-block stride (words): 16B aligned and % 8 == 4 so the
// 8-lane LDS.128 phases tile all 32 banks conflict-free.
template <int P> struct WStride { static constexpr int v = ((4 * 3 * P) % 8 == 4) ? (4 * 3 * P) : (4 * 3 * P + 4); };
template <> struct WStride<1> { static constexpr int v = 20; };

// Partial-sum scratch: per query region of PREG=240 words (240 % 32 == 16 so the
// two half-warps of a warp land on disjoint bank halves). Column j at [j*20, j*20+16).
#define PREG 240

// Divide-free staging: i indexes (c,k) as i = c*64 + k.
__device__ __forceinline__ void load_wb(float* sWb, float* sB, int STRIDE,
    const float* __restrict__ we, const float* __restrict__ be,
    const float* __restrict__ ww, const float* __restrict__ bw,
    int P, int tid, int nthreads)
{
    const int NCOL = 3 * P;
    for (int i = tid; i < 64 * NCOL; i += nthreads) {
        const int c = i >> 6, k = i & 63;
        float v = (c < 2 * P) ? we[k * (2 * P) + c] : ww[k * P + (c - 2 * P)];
        sWb[(k >> 2) * STRIDE + c * 4 + (k & 3)] = v;
    }
    if (tid < NCOL) sB[tid] = (tid < 2 * P) ? be[tid] : bw[tid - 2 * P];
}

// One stage for one query on a 16-lane half-warp; lane owns 4 channels (c4).
template <int P>
__device__ __forceinline__ float4 run_stage(
    float4 c4, int sl, int qw,
    const float* __restrict__ sWb,
    const float* __restrict__ sB,
    float* __restrict__ sPart,
    float* __restrict__ sLog,
    float& spx, float& spy,
    float base_x, float base_y, float sc_x, float sc_y,
    int h, int w,
    const float* __restrict__ vbase, bool active)
{
    constexpr int NCOL = 3 * P;
    constexpr int STRIDE = WStride<P>::v;

    // ---- register GEMM partials -> transpose-reduce scratch ----
    const float4* blk = reinterpret_cast<const float4*>(sWb + sl * STRIDE);
    float* myPart = sPart + qw * PREG;
    #pragma unroll
    for (int j = 0; j < NCOL; j++) {
        const float4 wv = blk[j];
        myPart[j * 20 + sl] =
            fmaf(c4.x, wv.x, fmaf(c4.y, wv.y, fmaf(c4.z, wv.z, c4.w * wv.w)));
    }
    __syncwarp();

    if (sl < NCOL) {
        const float4* col = reinterpret_cast<const float4*>(myPart + sl * 20);
        const float4 a = col[0], b = col[1], c = col[2], d = col[3];
        const float s = (((a.x + a.y) + (a.z + a.w)) + ((b.x + b.y) + (b.z + b.w)))
                      + (((c.x + c.y) + (c.z + c.w)) + ((d.x + d.y) + (d.z + d.w)));
        sLog[qw * 16 + sl] = s + sB[sl];
    }
    __syncwarp();

    float lg[NCOL];
    {
        const float4* lq = reinterpret_cast<const float4*>(sLog + qw * 16);
        #pragma unroll
        for (int v4 = 0; v4 < (NCOL + 3) / 4; v4++) {
            const float4 t = lq[v4];
            if (4 * v4 + 0 < NCOL) lg[4 * v4 + 0] = t.x;
            if (4 * v4 + 1 < NCOL) lg[4 * v4 + 1] = t.y;
            if (4 * v4 + 2 < NCOL) lg[4 * v4 + 2] = t.z;
            if (4 * v4 + 3 < NCOL) lg[4 * v4 + 3] = t.w;
        }
    }

    // ---- softmax + argmax over P (fast exp: MUFU path) ----
    float wl[P];
    float m = -1e30f; int mid = 0;
    #pragma unroll
    for (int p = 0; p < P; p++) {
        wl[p] = lg[2 * P + p];
        if (wl[p] > m) { m = wl[p]; mid = p; }   // strict > => first max (jnp.argmax)
    }
    float sum = 0.f;
    #pragma unroll
    for (int p = 0; p < P; p++) { wl[p] = __expf(wl[p] - m); sum += wl[p]; }
    const float inv = 1.0f / sum;

    // offsets use OLD speed; speed updated with delta[argmax]
    const float bx = fmaf(spx, sc_x, base_x);
    const float by = fmaf(spy, sc_y, base_y);
    spx += lg[2 * mid];
    spy += lg[2 * mid + 1];

    float4 acc = make_float4(0.f, 0.f, 0.f, 0.f);
    #pragma unroll
    for (int p = 0; p < P; p++) {
        const float x = fmaf(lg[2 * p],     sc_x, bx);
        const float y = fmaf(lg[2 * p + 1], sc_y, by);
        const float x0f = floorf(x), y0f = floorf(y);
        const float fx = x - x0f, fy = y - y0f;
        const int x0 = (int)x0f, y0 = (int)y0f;
        const int x1 = x0 + 1,   y1 = y0 + 1;

        const float wp = active ? wl[p] * inv : 0.f;
        // validity folded into axis weights (unsigned compare = 1 op each)
        const float wx0 = ((unsigned)x0 < (unsigned)w) ? (1.f - fx) : 0.f;
        const float wx1 = ((unsigned)x1 < (unsigned)w) ? fx         : 0.f;
        const float wy0 = ((unsigned)y0 < (unsigned)h) ? (1.f - fy) * wp : 0.f;
        const float wy1 = ((unsigned)y1 < (unsigned)h) ? fy * wp         : 0.f;

        const int xc0 = min(max(x0, 0), w - 1);
        const int xc1 = min(max(x1, 0), w - 1);
        const int r0 = min(max(y0, 0), h - 1) * w;
        const int r1 = min(max(y1, 0), h - 1) * w;

        const float4 v00 = *reinterpret_cast<const float4*>(vbase + (r0 + xc0) * 64);
        const float4 v01 = *reinterpret_cast<const float4*>(vbase + (r0 + xc1) * 64);
        const float4 v10 = *reinterpret_cast<const float4*>(vbase + (r1 + xc0) * 64);
        const float4 v11 = *reinterpret_cast<const float4*>(vbase + (r1 + xc1) * 64);

        const float c00 = wx0 * wy0, c01 = wx1 * wy0;
        const float c10 = wx0 * wy1, c11 = wx1 * wy1;

        acc.x = fmaf(v00.x, c00, acc.x); acc.y = fmaf(v00.y, c00, acc.y);
        acc.z = fmaf(v00.z, c00, acc.z); acc.w = fmaf(v00.w, c00, acc.w);
        acc.x = fmaf(v01.x, c01, acc.x); acc.y = fmaf(v01.y, c01, acc.y);
        acc.z = fmaf(v01.z, c01, acc.z); acc.w = fmaf(v01.w, c01, acc.w);
        acc.x = fmaf(v10.x, c10, acc.x); acc.y = fmaf(v10.y, c10, acc.y);
        acc.z = fmaf(v10.z, c10, acc.z); acc.w = fmaf(v10.w, c10, acc.w);
        acc.x = fmaf(v11.x, c11, acc.x); acc.y = fmaf(v11.y, c11, acc.y);
        acc.z = fmaf(v11.z, c11, acc.z); acc.w = fmaf(v11.w, c11, acc.w);
    }
    return acc;
}

template <int P1, int P2, int P3>
__global__ __launch_bounds__(256, 6) void speed_sampler_fused(
    const float* __restrict__ curIn,
    const float* __restrict__ indices,
    const float* __restrict__ value,
    const float* __restrict__ we1, const float* __restrict__ be1,
    const float* __restrict__ ww1, const float* __restrict__ bw1,
    const float* __restrict__ we2, const float* __restrict__ be2,
    const float* __restrict__ ww2, const float* __restrict__ bw2,
    const float* __restrict__ we3, const float* __restrict__ be3,
    const float* __restrict__ ww3, const float* __restrict__ bw3,
    const int* __restrict__ hsp_p, const int* __restrict__ wsp_p,
    float* __restrict__ out,
    int BFN, int BFHW)
{
    constexpr int S1 = WStride<P1>::v, S2 = WStride<P2>::v, S3 = WStride<P3>::v;
    __shared__ __align__(16) float sWb1[16 * S1];
    __shared__ __align__(16) float sWb2[16 * S2];
    __shared__ __align__(16) float sWb3[16 * S3];
    __shared__ float sB1[3 * P1], sB2[3 * P2], sB3[3 * P3];
    __shared__ __align__(16) float sPart[QPB * PREG];
    __shared__ __align__(16) float sLog[QPB * 16];

    const int tid = threadIdx.x;
    const int sl = tid & 15;
    const int qw = tid >> 4;
    const int q = blockIdx.x * QPB + qw;
    const int h = *hsp_p, w = *wsp_p;
    const int HW = h * w;
    const int BF = BFHW / HW;
    const int Nq = BFN / BF;
    const bool active = q < BFN;

    const float fh = (float)h, fw = (float)w;
    const float rwh = fw / fh, rhw = fh / fw;
    const float sc_x = 0.1f * rwh, sc_y = 0.1f * rhw;

    // ---- early loads + L1 prefetch of the base 2x2 neighborhood ----
    // Offsets are 0.1-scaled (sub-pixel), so all sampled points land in/near
    // the base coordinate's 2x2 patch; warming it here overlaps the DRAM
    // latency with weight staging + stage-1 GEMM. Hint only: harmless if wrong.
    float4 c4 = make_float4(0.f, 0.f, 0.f, 0.f);
    float base_x = -0.5f, base_y = -0.5f;
    const float* vbase = value + 4 * sl;
    if (active) {
        c4 = *reinterpret_cast<const float4*>(curIn + (size_t)q * 64 + 4 * sl);
        const float2 idx = *reinterpret_cast<const float2*>(indices + (size_t)q * 2);
        base_x = fmaf(idx.x, rwh, -0.5f);
        base_y = fmaf(idx.y, rhw, -0.5f);
        const int bf = q / Nq;
        vbase += (size_t)bf * HW * 64;

        const int px0 = (int)floorf(base_x), py0 = (int)floorf(base_y);
        const int pxc0 = min(max(px0, 0), w - 1);
        const int pxc1 = min(max(px0 + 1, 0), w - 1);
        const int pr0 = min(max(py0, 0), h - 1) * w;
        const int pr1 = min(max(py0 + 1, 0), h - 1) * w;
        asm volatile("prefetch.global.L1 [%0];" :: "l"(vbase + (pr0 + pxc0) * 64));
        asm volatile("prefetch.global.L1 [%0];" :: "l"(vbase + (pr0 + pxc1) * 64));
        asm volatile("prefetch.global.L1 [%0];" :: "l"(vbase + (pr1 + pxc0) * 64));
        asm volatile("prefetch.global.L1 [%0];" :: "l"(vbase + (pr1 + pxc1) * 64));
    }

    load_wb(sWb1, sB1, S1, we1, be1, ww1, bw1, P1, tid, blockDim.x);
    load_wb(sWb2, sB2, S2, we2, be2, ww2, bw2, P2, tid, blockDim.x);
    load_wb(sWb3, sB3, S3, we3, be3, ww3, bw3, P3, tid, blockDim.x);
    __syncthreads();

    float spx = 0.f, spy = 0.f;

    c4 = run_stage<P1>(c4, sl, qw, sWb1, sB1, sPart, sLog, spx, spy, base_x, base_y, sc_x, sc_y, h, w, vbase, active);
    c4 = run_stage<P2>(c4, sl, qw, sWb2, sB2, sPart, sLog, spx, spy, base_x, base_y, sc_x, sc_y, h, w, vbase, active);
    c4 = run_stage<P3>(c4, sl, qw, sWb3, sB3, sPart, sLog, spx, spy, base_x, base_y, sc_x, sc_y, h, w, vbase, active);

    if (active) {
        float* o = out + (size_t)q * 66 + 4 * sl;
        *reinterpret_cast<float2*>(o)     = make_float2(c4.x, c4.y);
        *reinterpret_cast<float2*>(o + 2) = make_float2(c4.z, c4.w);
        if (sl == 0) {
            out[(size_t)q * 66 + 64] = spx;
            out[(size_t)q * 66 + 65] = spy;
        }
    }
}

extern "C" void kernel_launch(void* const* d_in, const int* in_sizes, int n_in,
                              void* d_out, int out_size)
{
    const float* cur  = (const float*)d_in[0];
    const float* idxs = (const float*)d_in[1];
    const float* val  = (const float*)d_in[2];
    const int*   hsp  = (const int*)d_in[3];
    const int*   wsp  = (const int*)d_in[4];

    const int P1 = in_sizes[6] / 2;
    const int P2 = in_sizes[10] / 2;
    const int P3 = in_sizes[14] / 2;
    const int C  = in_sizes[5] / in_sizes[6];
    const int BFN  = in_sizes[0] / C;
    const int BFHW = in_sizes[2] / C;

    float* out = (float*)d_out;
    dim3 block(256);
    dim3 grid((BFN + QPB - 1) / QPB);

    if (P1 == 4 && P2 == 2 && P3 == 1) {
        speed_sampler_fused<4, 2, 1><<<grid, block>>>(
            cur, idxs, val,
            (const float*)d_in[5],  (const float*)d_in[6],
            (const float*)d_in[7],  (const float*)d_in[8],
            (const float*)d_in[9],  (const float*)d_in[10],
            (const float*)d_in[11], (const float*)d_in[12],
            (const float*)d_in[13], (const float*)d_in[14],
            (const float*)d_in[15], (const float*)d_in[16],
            hsp, wsp, out, BFN, BFHW);
    }
}